// round 10
// baseline (speedup 1.0000x reference)
#include <cuda_runtime.h>
#include <cuda_bf16.h>
#include <cstdint>

// Steerable encoder, fully fused single kernel:
//   out_c[r][j] = sum_i (ey[r][i]*w_c[i]) * ex[j][i]
// Grid (3 channels x 48 K-splits) = 144 CTAs, all co-resident (<=148 SMs).
// Each CTA materializes its own k-step operand tiles (bf16 hi/lo split) into
// smem in ldmatrix layout, runs HMMA, writes split partials, grid-barriers,
// then reduces + normalizes.

#define NA     128
#define NPIX   (NA * NA)
#define NPTS   8192
#define NSPLIT 48
#define KSTEPS 512                 // 8192 / 16
#define NCTAS  (3 * NSPLIT)        // 144
#define MAXI   192                 // max i's per CTA (11 steps * 16 = 176)

__device__ float g_part[3 * NSPLIT * NPIX];       // 9.4 MB
__device__ unsigned int g_arrive  = 0;
__device__ unsigned int g_release = 0;

// ---------------- helpers ----------------
__device__ __forceinline__ uint32_t smem_u32(const void* p) {
    uint32_t a;
    asm("{ .reg .u64 t; cvta.to.shared.u64 t, %1; cvt.u32.u64 %0, t; }" : "=r"(a) : "l"(p));
    return a;
}
__device__ __forceinline__ void ldsm4(uint32_t addr, uint32_t& r0, uint32_t& r1,
                                      uint32_t& r2, uint32_t& r3) {
    asm volatile("ldmatrix.sync.aligned.m8n8.x4.shared.b16 {%0,%1,%2,%3}, [%4];"
                 : "=r"(r0), "=r"(r1), "=r"(r2), "=r"(r3) : "r"(addr));
}
__device__ __forceinline__ void mma_bf16(float* d, const uint32_t* a, const uint32_t* b) {
    asm volatile("mma.sync.aligned.m16n8k16.row.col.f32.bf16.bf16.f32 "
                 "{%0,%1,%2,%3}, {%4,%5,%6,%7}, {%8,%9}, {%0,%1,%2,%3};"
                 : "+f"(d[0]), "+f"(d[1]), "+f"(d[2]), "+f"(d[3])
                 : "r"(a[0]), "r"(a[1]), "r"(a[2]), "r"(a[3]), "r"(b[0]), "r"(b[1]));
}
// Split pair (a=even i, b=odd i) -> packed bf16x2 hi (truncated) and lo (residual).
__device__ __forceinline__ void pack_pair(float a, float b, uint32_t& hi, uint32_t& lo) {
    uint32_t ua = __float_as_uint(a), ub = __float_as_uint(b);
    hi = __byte_perm(ua, ub, 0x7632);
    float la = a - __uint_as_float(ua & 0xFFFF0000u);
    float lb = b - __uint_as_float(ub & 0xFFFF0000u);
    asm("cvt.rn.bf16x2.f32 %0, %1, %2;" : "=r"(lo) : "f"(lb), "f"(la));
}

// ---------------- fused kernel ----------------
// smem stage (16KB): Ah@0, Al@4096, Bh@8192, Bl@12288; each [kg(2)][row(128)][16B]
__global__ __launch_bounds__(256)
void fused_kernel(const float* __restrict__ X, const float* __restrict__ Y,
                  float* __restrict__ out)
{
    __shared__ __align__(16) char stage[16384];
    __shared__ float spx[MAXI], spy[MAXI], sy0[MAXI], sy1[MAXI];
    __shared__ unsigned int sh_rel0;

    const uint32_t sb = smem_u32(stage);
    const int tid = threadIdx.x;
    const int lane = tid & 31, wid = tid >> 5;
    const int c = blockIdx.x, s = blockIdx.y;
    const int lo = (KSTEPS * s) / NSPLIT, hi = (KSTEPS * (s + 1)) / NSPLIT;
    const int cnt = (hi - lo) * 16;

    if (tid == 0) sh_rel0 = *(volatile unsigned int*)&g_release;

    // stage this CTA's point parameters
    for (int idx = tid; idx < cnt; idx += 256) {
        int i = lo * 16 + idx;
        float2 xp = ((const float2*)X)[i];
        float2 yp = ((const float2*)Y)[i];
        spx[idx] = xp.x; spy[idx] = xp.y;
        sy0[idx] = yp.x; sy1[idx] = yp.y;
    }

    const float step = 4.0f / 127.0f;
    const int row = tid & 127, g = tid >> 7;      // materializer role
    const float yk = 2.0f - (float)row * step;
    const float xj = -2.0f + (float)row * step;

    // MMA role
    const int wm = wid & 3, wn = wid >> 2;        // warp tile rows [wm*32), cols [wn*64)
    const int q = lane >> 3, rin = lane & 7;

    float acc[2][8][4];
    #pragma unroll
    for (int a = 0; a < 2; a++)
        #pragma unroll
        for (int b = 0; b < 8; b++)
            #pragma unroll
            for (int d = 0; d < 4; d++) acc[a][b][d] = 0.0f;

    __syncthreads();

    for (int ks = lo; ks < hi; ks++) {
        // ---- materialize stage for this k-step ----
        const int lb = (ks - lo) * 16 + g * 8;
        {
            // A side: ey * w_c  (hi/lo)
            float e[8];
            #pragma unroll
            for (int u = 0; u < 8; u++) {
                float dy = yk - spy[lb + u];
                e[u] = __expf(-0.5f * dy * dy);
            }
            float w[8];
            if (c == 0) {
                #pragma unroll
                for (int u = 0; u < 8; u++) w[u] = e[u];
            } else if (c == 1) {
                #pragma unroll
                for (int u = 0; u < 8; u++) w[u] = e[u] * sy0[lb + u];
            } else {
                #pragma unroll
                for (int u = 0; u < 8; u++) w[u] = e[u] * sy1[lb + u];
            }
            uint32_t hw[4], lw[4];
            #pragma unroll
            for (int ee = 0; ee < 4; ee++)
                pack_pair(w[2 * ee], w[2 * ee + 1], hw[ee], lw[ee]);
            ((uint4*)(stage))[g * 128 + row]          = make_uint4(hw[0], hw[1], hw[2], hw[3]);
            ((uint4*)(stage + 4096))[g * 128 + row]   = make_uint4(lw[0], lw[1], lw[2], lw[3]);

            // B side: ex (hi/lo)
            float eb[8];
            #pragma unroll
            for (int u = 0; u < 8; u++) {
                float dx = xj - spx[lb + u];
                eb[u] = __expf(-0.5f * dx * dx);
            }
            #pragma unroll
            for (int ee = 0; ee < 4; ee++)
                pack_pair(eb[2 * ee], eb[2 * ee + 1], hw[ee], lw[ee]);
            ((uint4*)(stage + 8192))[g * 128 + row]   = make_uint4(hw[0], hw[1], hw[2], hw[3]);
            ((uint4*)(stage + 12288))[g * 128 + row]  = make_uint4(lw[0], lw[1], lw[2], lw[3]);
        }
        __syncthreads();

        // ---- MMA from smem ----
        uint32_t ah[2][4], al[2][4];
        #pragma unroll
        for (int mt = 0; mt < 2; mt++) {
            int rr = (wm * 2 + mt) * 16 + (q & 1) * 8 + rin;
            uint32_t ad = sb + ((q >> 1) * 128 + rr) * 16;
            ldsm4(ad,        ah[mt][0], ah[mt][1], ah[mt][2], ah[mt][3]);
            ldsm4(ad + 4096, al[mt][0], al[mt][1], al[mt][2], al[mt][3]);
        }
        #pragma unroll
        for (int d = 0; d < 4; d++) {
            int jj = wn * 64 + d * 16 + (q >> 1) * 8 + rin;
            uint32_t bd = sb + 8192 + ((q & 1) * 128 + jj) * 16;
            uint32_t bh[4], bl[4];
            ldsm4(bd,        bh[0], bh[1], bh[2], bh[3]);
            ldsm4(bd + 4096, bl[0], bl[1], bl[2], bl[3]);
            #pragma unroll
            for (int half = 0; half < 2; half++) {
                uint32_t bhp[2] = { bh[2 * half], bh[2 * half + 1] };
                uint32_t blp[2] = { bl[2 * half], bl[2 * half + 1] };
                #pragma unroll
                for (int mt = 0; mt < 2; mt++) {
                    float* D = acc[mt][2 * d + half];
                    mma_bf16(D, ah[mt], bhp);
                    mma_bf16(D, ah[mt], blp);
                    mma_bf16(D, al[mt], bhp);
                }
            }
        }
        __syncthreads();
    }

    // ---- write partial plane [c][s][r][j] ----
    float* plane = g_part + (c * NSPLIT + s) * NPIX;
    const int gid = lane >> 2, tig = lane & 3;
    #pragma unroll
    for (int mt = 0; mt < 2; mt++) {
        #pragma unroll
        for (int nt = 0; nt < 8; nt++) {
            int m0 = wm * 32 + mt * 16 + gid;
            int j0 = wn * 64 + nt * 8 + 2 * tig;
            *(float2*)(plane + m0 * NA + j0)       = make_float2(acc[mt][nt][0], acc[mt][nt][1]);
            *(float2*)(plane + (m0 + 8) * NA + j0) = make_float2(acc[mt][nt][2], acc[mt][nt][3]);
        }
    }

    // ---- grid barrier (all 144 CTAs co-resident) ----
    __threadfence();
    __syncthreads();
    if (tid == 0) {
        unsigned int old = atomicAdd(&g_arrive, 1u);
        if (old == NCTAS - 1) {
            g_arrive = 0;
            __threadfence();
            atomicAdd(&g_release, 1u);
        }
        while (*(volatile unsigned int*)&g_release == sh_rel0) { }
    }
    __syncthreads();
    __threadfence();

    // ---- fused reduce + normalize (partials L2-hot) ----
    const int bid = blockIdx.y * gridDim.x + blockIdx.x;    // 0..143
    const int p = bid * 256 + tid;
    if (p < NPIX) {
        float s0 = 0.0f, s1 = 0.0f, s2 = 0.0f;
        #pragma unroll
        for (int sl = 0; sl < NSPLIT; sl++) {
            s0 += __ldcg(&g_part[(0 * NSPLIT + sl) * NPIX + p]);
            s1 += __ldcg(&g_part[(1 * NSPLIT + sl) * NPIX + p]);
            s2 += __ldcg(&g_part[(2 * NSPLIT + sl) * NPIX + p]);
        }
        float r = 1.0f / s0;
        out[p]            = s0;
        out[NPIX + p]     = s1 * r;
        out[2 * NPIX + p] = s2 * r;
    }
}

extern "C" void kernel_launch(void* const* d_in, const int* in_sizes, int n_in,
                              void* d_out, int out_size)
{
    const float* X = (const float*)d_in[0];
    const float* Y = (const float*)d_in[1];
    float* out = (float*)d_out;

    fused_kernel<<<dim3(3, NSPLIT), 256>>>(X, Y, out);
}

// round 11
// speedup vs baseline: 1.0015x; 1.0015x over previous
#include <cuda_runtime.h>
#include <cuda_bf16.h>
#include <cstdint>

// Steerable encoder, fully fused single kernel (double-buffered, occ 2):
//   out_c[r][j] = sum_i (ey[r][i]*w_c[i]) * ex[j][i]
// Grid (3 channels x 96 K-splits) = 288 CTAs, all co-resident at occ 2.
// Each CTA materializes its k-step operand tiles (bf16 hi/lo split) into a
// double-buffered smem stage (overlapped with HMMA on the other buffer),
// writes split partials, grid-barriers, then reduces + normalizes.

#define NA     128
#define NPIX   (NA * NA)
#define NPTS   8192
#define NSPLIT 96
#define KSTEPS 512                 // 8192 / 16
#define NCTAS  (3 * NSPLIT)        // 288 (<= 148*2 residency)
#define MAXI   96                  // max i's per CTA (6 steps * 16)

__device__ float g_part[3 * NSPLIT * NPIX];       // 18.9 MB
__device__ unsigned int g_arrive  = 0;
__device__ unsigned int g_release = 0;

// ---------------- helpers ----------------
__device__ __forceinline__ uint32_t smem_u32(const void* p) {
    uint32_t a;
    asm("{ .reg .u64 t; cvta.to.shared.u64 t, %1; cvt.u32.u64 %0, t; }" : "=r"(a) : "l"(p));
    return a;
}
__device__ __forceinline__ void ldsm4(uint32_t addr, uint32_t& r0, uint32_t& r1,
                                      uint32_t& r2, uint32_t& r3) {
    asm volatile("ldmatrix.sync.aligned.m8n8.x4.shared.b16 {%0,%1,%2,%3}, [%4];"
                 : "=r"(r0), "=r"(r1), "=r"(r2), "=r"(r3) : "r"(addr));
}
__device__ __forceinline__ void mma_bf16(float* d, const uint32_t* a, const uint32_t* b) {
    asm volatile("mma.sync.aligned.m16n8k16.row.col.f32.bf16.bf16.f32 "
                 "{%0,%1,%2,%3}, {%4,%5,%6,%7}, {%8,%9}, {%0,%1,%2,%3};"
                 : "+f"(d[0]), "+f"(d[1]), "+f"(d[2]), "+f"(d[3])
                 : "r"(a[0]), "r"(a[1]), "r"(a[2]), "r"(a[3]), "r"(b[0]), "r"(b[1]));
}
// Split pair (a=even i, b=odd i) -> packed bf16x2 hi (truncated) and lo (residual).
__device__ __forceinline__ void pack_pair(float a, float b, uint32_t& hi, uint32_t& lo) {
    uint32_t ua = __float_as_uint(a), ub = __float_as_uint(b);
    hi = __byte_perm(ua, ub, 0x7632);
    float la = a - __uint_as_float(ua & 0xFFFF0000u);
    float lb = b - __uint_as_float(ub & 0xFFFF0000u);
    asm("cvt.rn.bf16x2.f32 %0, %1, %2;" : "=r"(lo) : "f"(lb), "f"(la));
}

// ---------------- fused kernel ----------------
// stage buffer (16KB each): Ah@0, Al@4096, Bh@8192, Bl@12288; [kg(2)][row(128)][16B]
__global__ __launch_bounds__(256, 2)
void fused_kernel(const float* __restrict__ X, const float* __restrict__ Y,
                  float* __restrict__ out)
{
    __shared__ __align__(16) char stage[2][16384];
    __shared__ float spx[MAXI], spy[MAXI], sy0[MAXI], sy1[MAXI];
    __shared__ unsigned int sh_rel0;

    const int tid = threadIdx.x;
    const int lane = tid & 31, wid = tid >> 5;
    const int c = blockIdx.x, s = blockIdx.y;
    const int lo = (KSTEPS * s) / NSPLIT, hi = (KSTEPS * (s + 1)) / NSPLIT;
    const int cnt = (hi - lo) * 16;

    if (tid == 0) sh_rel0 = *(volatile unsigned int*)&g_release;

    // stage this CTA's point parameters
    for (int idx = tid; idx < cnt; idx += 256) {
        int i = lo * 16 + idx;
        float2 xp = ((const float2*)X)[i];
        float2 yp = ((const float2*)Y)[i];
        spx[idx] = xp.x; spy[idx] = xp.y;
        sy0[idx] = yp.x; sy1[idx] = yp.y;
    }

    const float step = 4.0f / 127.0f;
    const int row = tid & 127, g = tid >> 7;      // materializer role
    const float yk = 2.0f - (float)row * step;
    const float xj = -2.0f + (float)row * step;

    // MMA role
    const int wm = wid & 3, wn = wid >> 2;        // warp tile rows [wm*32), cols [wn*64)
    const int q = lane >> 3, rin = lane & 7;

    float acc[2][8][4];
    #pragma unroll
    for (int a = 0; a < 2; a++)
        #pragma unroll
        for (int b = 0; b < 8; b++)
            #pragma unroll
            for (int d = 0; d < 4; d++) acc[a][b][d] = 0.0f;

    __syncthreads();

    // materialize one k-step's tiles into a buffer
    auto materialize = [&](char* buf, int ks) {
        const int lb = (ks - lo) * 16 + g * 8;
        float e[8];
        #pragma unroll
        for (int u = 0; u < 8; u++) {
            float dy = yk - spy[lb + u];
            e[u] = __expf(-0.5f * dy * dy);
        }
        float w[8];
        if (c == 0) {
            #pragma unroll
            for (int u = 0; u < 8; u++) w[u] = e[u];
        } else if (c == 1) {
            #pragma unroll
            for (int u = 0; u < 8; u++) w[u] = e[u] * sy0[lb + u];
        } else {
            #pragma unroll
            for (int u = 0; u < 8; u++) w[u] = e[u] * sy1[lb + u];
        }
        uint32_t hw[4], lw[4];
        #pragma unroll
        for (int ee = 0; ee < 4; ee++)
            pack_pair(w[2 * ee], w[2 * ee + 1], hw[ee], lw[ee]);
        ((uint4*)(buf))[g * 128 + row]         = make_uint4(hw[0], hw[1], hw[2], hw[3]);
        ((uint4*)(buf + 4096))[g * 128 + row]  = make_uint4(lw[0], lw[1], lw[2], lw[3]);

        float eb[8];
        #pragma unroll
        for (int u = 0; u < 8; u++) {
            float dx = xj - spx[lb + u];
            eb[u] = __expf(-0.5f * dx * dx);
        }
        #pragma unroll
        for (int ee = 0; ee < 4; ee++)
            pack_pair(eb[2 * ee], eb[2 * ee + 1], hw[ee], lw[ee]);
        ((uint4*)(buf + 8192))[g * 128 + row]  = make_uint4(hw[0], hw[1], hw[2], hw[3]);
        ((uint4*)(buf + 12288))[g * 128 + row] = make_uint4(lw[0], lw[1], lw[2], lw[3]);
    };

    materialize(stage[0], lo);
    __syncthreads();

    for (int ks = lo; ks < hi; ks++) {
        const int buf = (ks - lo) & 1;
        // overlap: fill next buffer while MMAs consume current one
        if (ks + 1 < hi) materialize(stage[buf ^ 1], ks + 1);

        const uint32_t base = smem_u32(stage[buf]);
        uint32_t ah[2][4], al[2][4];
        #pragma unroll
        for (int mt = 0; mt < 2; mt++) {
            int rr = (wm * 2 + mt) * 16 + (q & 1) * 8 + rin;
            uint32_t ad = base + ((q >> 1) * 128 + rr) * 16;
            ldsm4(ad,        ah[mt][0], ah[mt][1], ah[mt][2], ah[mt][3]);
            ldsm4(ad + 4096, al[mt][0], al[mt][1], al[mt][2], al[mt][3]);
        }
        #pragma unroll
        for (int d = 0; d < 4; d++) {
            int jj = wn * 64 + d * 16 + (q >> 1) * 8 + rin;
            uint32_t bd = base + 8192 + ((q & 1) * 128 + jj) * 16;
            uint32_t bh[4], bl[4];
            ldsm4(bd,        bh[0], bh[1], bh[2], bh[3]);
            ldsm4(bd + 4096, bl[0], bl[1], bl[2], bl[3]);
            #pragma unroll
            for (int half = 0; half < 2; half++) {
                uint32_t bhp[2] = { bh[2 * half], bh[2 * half + 1] };
                uint32_t blp[2] = { bl[2 * half], bl[2 * half + 1] };
                #pragma unroll
                for (int mt = 0; mt < 2; mt++) {
                    float* D = acc[mt][2 * d + half];
                    mma_bf16(D, ah[mt], bhp);
                    mma_bf16(D, ah[mt], blp);
                    mma_bf16(D, al[mt], bhp);
                }
            }
        }
        __syncthreads();
    }

    // ---- write partial plane [c][s][r][j] ----
    float* plane = g_part + (c * NSPLIT + s) * NPIX;
    const int gid = lane >> 2, tig = lane & 3;
    #pragma unroll
    for (int mt = 0; mt < 2; mt++) {
        #pragma unroll
        for (int nt = 0; nt < 8; nt++) {
            int m0 = wm * 32 + mt * 16 + gid;
            int j0 = wn * 64 + nt * 8 + 2 * tig;
            *(float2*)(plane + m0 * NA + j0)       = make_float2(acc[mt][nt][0], acc[mt][nt][1]);
            *(float2*)(plane + (m0 + 8) * NA + j0) = make_float2(acc[mt][nt][2], acc[mt][nt][3]);
        }
    }

    // ---- grid barrier (all 288 CTAs co-resident at occ 2) ----
    __threadfence();
    __syncthreads();
    if (tid == 0) {
        unsigned int old = atomicAdd(&g_arrive, 1u);
        if (old == NCTAS - 1) {
            g_arrive = 0;
            __threadfence();
            atomicAdd(&g_release, 1u);
        }
        while (*(volatile unsigned int*)&g_release == sh_rel0) { }
    }
    __syncthreads();
    __threadfence();

    // ---- fused reduce + normalize (partials L2-hot) ----
    const int bid = blockIdx.y * gridDim.x + blockIdx.x;    // 0..287
    const int p = bid * 256 + tid;
    if (p < NPIX) {
        float s0 = 0.0f, s1 = 0.0f, s2 = 0.0f;
        #pragma unroll 12
        for (int sl = 0; sl < NSPLIT; sl++) {
            s0 += __ldcg(&g_part[(0 * NSPLIT + sl) * NPIX + p]);
            s1 += __ldcg(&g_part[(1 * NSPLIT + sl) * NPIX + p]);
            s2 += __ldcg(&g_part[(2 * NSPLIT + sl) * NPIX + p]);
        }
        float r = 1.0f / s0;
        out[p]            = s0;
        out[NPIX + p]     = s1 * r;
        out[2 * NPIX + p] = s2 * r;
    }
}

extern "C" void kernel_launch(void* const* d_in, const int* in_sizes, int n_in,
                              void* d_out, int out_size)
{
    const float* X = (const float*)d_in[0];
    const float* Y = (const float*)d_in[1];
    float* out = (float*)d_out;

    fused_kernel<<<dim3(3, NSPLIT), 256>>>(X, Y, out);
}